// round 1
// baseline (speedup 1.0000x reference)
#include <cuda_runtime.h>

#define Bsz 16
#define Tsz 2048
#define WN  512
#define Dd  300
#define DP  308   // padded row stride in smem (mod 32 = 20 -> <=2-way bank conflicts)
#define TT  64    // t-rows per CTA
#define WC  64    // w-chunk
#define PP  68    // probs row stride
#define NT  256

// scratch for proj = attn @ W_h^T  (bias dropped: constant per t-row, softmax-invariant)
__device__ float g_proj[2u * Bsz * WN * Dd];

// ---------------------------------------------------------------------------
// proj kernel: proj[h][b][w][d] = sum_k attn[b][w][k] * W_h[d][k]
// 64x64 tile, K staged 32 at a time, 4x4 micro-tiles.
// ---------------------------------------------------------------------------
__global__ __launch_bounds__(NT, 1) void proj_kernel(
    const float* __restrict__ attn,
    const float* __restrict__ W2,
    const float* __restrict__ W3)
{
    __shared__ float sA[64 * 36];
    __shared__ float sB[64 * 36];
    const int h = blockIdx.z & 1, b = blockIdx.z >> 1;
    const float* Wm = h ? W3 : W2;
    const int w0 = blockIdx.x * 64, d0 = blockIdx.y * 64;
    const int tid = threadIdx.x, txS = tid & 15, tyS = tid >> 4;
    const float* A = attn + (size_t)b * WN * Dd;

    float c[4][4];
#pragma unroll
    for (int i = 0; i < 4; i++)
#pragma unroll
        for (int j = 0; j < 4; j++) c[i][j] = 0.f;

    for (int k0 = 0; k0 < Dd; k0 += 32) {
        __syncthreads();
        for (int i = tid; i < 64 * 8; i += NT) {
            int r = i >> 3, c4 = i & 7, k = k0 + c4 * 4;
            float4 v = make_float4(0.f, 0.f, 0.f, 0.f);
            if (k < Dd) v = *(const float4*)(A + (size_t)(w0 + r) * Dd + k);
            *(float4*)&sA[r * 36 + c4 * 4] = v;
        }
        for (int i = tid; i < 64 * 8; i += NT) {
            int r = i >> 3, c4 = i & 7, k = k0 + c4 * 4, d = d0 + r;
            float4 v = make_float4(0.f, 0.f, 0.f, 0.f);
            if (k < Dd && d < Dd) v = *(const float4*)(Wm + (size_t)d * Dd + k);
            *(float4*)&sB[r * 36 + c4 * 4] = v;
        }
        __syncthreads();
#pragma unroll
        for (int k = 0; k < 32; k += 4) {
            float4 a4[4], b4[4];
#pragma unroll
            for (int i = 0; i < 4; i++) a4[i] = *(float4*)&sA[(tyS + 16 * i) * 36 + k];
#pragma unroll
            for (int j = 0; j < 4; j++) b4[j] = *(float4*)&sB[(txS + 16 * j) * 36 + k];
#pragma unroll
            for (int i = 0; i < 4; i++)
#pragma unroll
                for (int j = 0; j < 4; j++) {
                    c[i][j] += a4[i].x * b4[j].x;
                    c[i][j] += a4[i].y * b4[j].y;
                    c[i][j] += a4[i].z * b4[j].z;
                    c[i][j] += a4[i].w * b4[j].w;
                }
        }
    }
    float* P = g_proj + ((size_t)h * Bsz + b) * WN * Dd;
#pragma unroll
    for (int i = 0; i < 4; i++) {
        int w = w0 + tyS + 16 * i;
#pragma unroll
        for (int j = 0; j < 4; j++) {
            int d = d0 + txS + 16 * j;
            if (d < Dd) P[(size_t)w * Dd + d] = c[i][j];
        }
    }
}

// ---------------------------------------------------------------------------
// fused attend kernel (flash-style, fp32):
//   grid (T/64, B, 2 heads), 256 threads, 1 CTA/SM (171 KB smem)
//   per chunk of 64 windows: S = main_tile @ proj_chunk^T (4x4 micro),
//   online softmax (shfl over 16-lane row groups), acc += P @ attn_chunk
//   (register acc: 4 rows x 19 d-cols per thread).
// ---------------------------------------------------------------------------
__global__ __launch_bounds__(NT, 1) void attend_kernel(
    const float* __restrict__ x1,   // [B,T,D]
    const float* __restrict__ x2,   // [B,WN,D]
    float* __restrict__ out)        // [2,B,T,D]
{
    extern __shared__ float sm[];
    float* sMain  = sm;               // TT*DP
    float* sChunk = sm + TT * DP;     // WC*DP (proj, then attn)
    float* sP     = sm + 2 * TT * DP; // TT*PP
    const int t0 = blockIdx.x * TT, b = blockIdx.y, h = blockIdx.z;
    const int tid = threadIdx.x, txS = tid & 15, tyS = tid >> 4;

    const float* mainB = x1 + ((size_t)b * Tsz + t0) * Dd;
    const float* attnB = x2 + (size_t)b * WN * Dd;
    const float* projB = g_proj + ((size_t)h * Bsz + b) * WN * Dd;

    for (int i = tid; i < TT * 75; i += NT) {
        int r = i / 75, c4 = i % 75;
        *(float4*)&sMain[r * DP + c4 * 4] = *(const float4*)(mainB + (size_t)r * Dd + c4 * 4);
    }

    float acc[4][19];
    float m_i[4], l_i[4];
#pragma unroll
    for (int i = 0; i < 4; i++) {
        m_i[i] = -1e30f; l_i[i] = 0.f;
#pragma unroll
        for (int j = 0; j < 19; j++) acc[i][j] = 0.f;
    }

    for (int w0 = 0; w0 < WN; w0 += WC) {
        __syncthreads();  // previous chunk's readers of sChunk are done
        for (int i = tid; i < WC * 75; i += NT) {
            int r = i / 75, c4 = i % 75;
            *(float4*)&sChunk[r * DP + c4 * 4] =
                *(const float4*)(projB + (size_t)(w0 + r) * Dd + c4 * 4);
        }
        __syncthreads();

        // --- scores: S[4][4] in registers ---
        float s[4][4];
#pragma unroll
        for (int i = 0; i < 4; i++)
#pragma unroll
            for (int j = 0; j < 4; j++) s[i][j] = 0.f;

#pragma unroll 3
        for (int k = 0; k < Dd; k += 4) {
            float4 a4[4], b4[4];
#pragma unroll
            for (int i = 0; i < 4; i++) a4[i] = *(float4*)&sMain[(tyS + 16 * i) * DP + k];
#pragma unroll
            for (int j = 0; j < 4; j++) b4[j] = *(float4*)&sChunk[(txS + 16 * j) * DP + k];
#pragma unroll
            for (int i = 0; i < 4; i++)
#pragma unroll
                for (int j = 0; j < 4; j++) {
                    s[i][j] += a4[i].x * b4[j].x;
                    s[i][j] += a4[i].y * b4[j].y;
                    s[i][j] += a4[i].z * b4[j].z;
                    s[i][j] += a4[i].w * b4[j].w;
                }
        }

        // --- online softmax over this chunk (row groups = 16 lanes same tyS) ---
#pragma unroll
        for (int i = 0; i < 4; i++) {
            float cmax = fmaxf(fmaxf(s[i][0], s[i][1]), fmaxf(s[i][2], s[i][3]));
#pragma unroll
            for (int o = 8; o >= 1; o >>= 1)
                cmax = fmaxf(cmax, __shfl_xor_sync(0xffffffffu, cmax, o));
            float newm = fmaxf(m_i[i], cmax);
            float alpha = __expf(m_i[i] - newm);
            float csum = 0.f;
#pragma unroll
            for (int j = 0; j < 4; j++) {
                float p = __expf(s[i][j] - newm);
                s[i][j] = p; csum += p;
            }
#pragma unroll
            for (int o = 8; o >= 1; o >>= 1)
                csum += __shfl_xor_sync(0xffffffffu, csum, o);
            l_i[i] = l_i[i] * alpha + csum;
            m_i[i] = newm;
#pragma unroll
            for (int j = 0; j < 19; j++) acc[i][j] *= alpha;
#pragma unroll
            for (int j = 0; j < 4; j++)
                sP[(tyS + 16 * i) * PP + txS + 16 * j] = s[i][j];
        }
        __syncthreads();  // sP complete; sChunk (proj) no longer needed

        // --- load attn chunk into sChunk ---
        for (int i = tid; i < WC * 75; i += NT) {
            int r = i / 75, c4 = i % 75;
            *(float4*)&sChunk[r * DP + c4 * 4] =
                *(const float4*)(attnB + (size_t)(w0 + r) * Dd + c4 * 4);
        }
        __syncthreads();

        // --- acc += P @ attn_chunk ---
#pragma unroll 2
        for (int w = 0; w < WC; w++) {
            float p0 = sP[(tyS     ) * PP + w];
            float p1 = sP[(tyS + 16) * PP + w];
            float p2 = sP[(tyS + 32) * PP + w];
            float p3 = sP[(tyS + 48) * PP + w];
            const float* ar = &sChunk[w * DP + txS * 19];
#pragma unroll
            for (int j = 0; j < 19; j++) {
                float av = ar[j];
                acc[0][j] += p0 * av;
                acc[1][j] += p1 * av;
                acc[2][j] += p2 * av;
                acc[3][j] += p3 * av;
            }
        }
    }

    // --- epilogue: normalize, stage through sMain, coalesced store ---
    float inv[4];
#pragma unroll
    for (int i = 0; i < 4; i++) inv[i] = 1.0f / l_i[i];
#pragma unroll
    for (int i = 0; i < 4; i++)
#pragma unroll
        for (int j = 0; j < 19; j++)
            sMain[(tyS + 16 * i) * DP + txS * 19 + j] = acc[i][j] * inv[i];
    __syncthreads();
    float* outB = out + (((size_t)h * Bsz + b) * Tsz + t0) * Dd;
    for (int i = tid; i < TT * 75; i += NT) {
        int r = i / 75, c4 = i % 75;
        *(float4*)(outB + (size_t)r * Dd + c4 * 4) = *(float4*)&sMain[r * DP + c4 * 4];
    }
}

// ---------------------------------------------------------------------------
extern "C" void kernel_launch(void* const* d_in, const int* in_sizes, int n_in,
                              void* d_out, int out_size)
{
    const float* x1 = (const float*)d_in[0];  // input1 [16,2048,300]
    const float* x2 = (const float*)d_in[1];  // input2 [16,512,300]
    const float* W2 = (const float*)d_in[2];  // [300,300]
    // d_in[3] = b2 (unused: softmax-invariant)
    const float* W3 = (const float*)d_in[4];  // [300,300]
    // d_in[5] = b3 (unused), d_in[6] = mode (always 1)
    float* out = (float*)d_out;               // [2,16,2048,300]

    proj_kernel<<<dim3(WN / 64, (Dd + 63) / 64, Bsz * 2), NT>>>(x2, W2, W3);

    size_t smem = (size_t)(2 * TT * DP + TT * PP) * sizeof(float);  // 175104 B
    cudaFuncSetAttribute(attend_kernel,
                         cudaFuncAttributeMaxDynamicSharedMemorySize, (int)smem);
    attend_kernel<<<dim3(Tsz / TT, Bsz, 2), NT, smem>>>(x1, x2, out);
}